// round 7
// baseline (speedup 1.0000x reference)
#include <cuda_runtime.h>
#include <cstdint>

// T=4 tables, E=1e6 rows, D=128 dim, B=8192 bags, L=32 per bag.
// indices: int32 [T,B,L] (1,048,576 el)   weights: f32 [T,E,D] (512,000,000 el)
// out: f32 [B, T*D]
//
// Established (R3/R4): HBM-gather bound, pinned at ~6230 GB/s (LTS structural
// cap) at any occupancy/MLP -> keep the lean 32-reg warp-per-bag shape.
// This round: exact-division persistent grid (8192 warps x exactly 4 bags
// each, fixed unrolled loop -> no ragged tail, no divergent loop guard).
// Warp w handles bags {w, w+8192, w+16384, w+24576} = same b, tables 0..3:
// the 4 output float4 stores per lane fall in one contiguous 2KB span.

namespace {
constexpr int T = 4;
constexpr long long E = 1000000;
constexpr int D = 128;
constexpr int B = 8192;
constexpr int L = 32;
constexpr int D4 = D / 4;            // 32 float4 per row -> one per lane
constexpr int WARPS_PER_BLOCK = 8;
constexpr int THREADS = WARPS_PER_BLOCK * 32;
constexpr int NUM_BAGS = T * B;      // 32768
constexpr long long IDX_ELEMS = (long long)T * B * L;
constexpr int GRID_BLOCKS = 1024;                       // 8192 warps
constexpr int TOTAL_WARPS = GRID_BLOCKS * WARPS_PER_BLOCK;
constexpr int BAGS_PER_WARP = NUM_BAGS / TOTAL_WARPS;   // exactly 4
}

__global__ __launch_bounds__(THREADS)
void embedding_bag_sum_kernel(const int* __restrict__ indices,
                              const float4* __restrict__ weights,
                              float4* __restrict__ out)
{
    const int lane = threadIdx.x & 31;
    const int warp_global = blockIdx.x * WARPS_PER_BLOCK + (threadIdx.x >> 5);

    // warp_global == b (batch element); iteration k == table t.
    const int b = warp_global;

    #pragma unroll
    for (int t = 0; t < BAGS_PER_WARP; ++t) {
        const int bag = t * TOTAL_WARPS + b;   // == t*B + b since TOTAL_WARPS==B

        // Each lane holds one of the 32 bag indices; broadcast via shfl.
        const int my_idx = __ldg(indices + (size_t)bag * L + lane);
        const float4* wt = weights + (size_t)t * (size_t)E * D4;

        float4 acc = make_float4(0.f, 0.f, 0.f, 0.f);

        #pragma unroll
        for (int j = 0; j < L; ++j) {
            const int row = __shfl_sync(0xffffffffu, my_idx, j);
            const float4 v = __ldg(wt + (size_t)row * D4 + lane);
            acc.x += v.x;
            acc.y += v.y;
            acc.z += v.z;
            acc.w += v.w;
        }

        out[((size_t)b * T + t) * D4 + lane] = acc;
    }
}

extern "C" void kernel_launch(void* const* d_in, const int* in_sizes, int n_in,
                              void* d_out, int out_size)
{
    const int*    indices = nullptr;
    const float4* weights = nullptr;
    for (int i = 0; i < n_in; ++i) {
        if ((long long)in_sizes[i] == IDX_ELEMS)
            indices = (const int*)d_in[i];
        else
            weights = (const float4*)d_in[i];
    }
    float4* out = (float4*)d_out;

    embedding_bag_sum_kernel<<<GRID_BLOCKS, THREADS>>>(indices, weights, out);
}

// round 8
// speedup vs baseline: 1.0904x; 1.0904x over previous
#include <cuda_runtime.h>
#include <cstdint>

// T=4 tables, E=1e6 rows, D=128 dim, B=8192 bags, L=32 per bag.
// indices: int32 [T,B,L] (1,048,576 el)   weights: f32 [T,E,D] (512,000,000 el)
// out: f32 [B, T*D]
//
// Evidence so far:
//   R3: 4096 blk x 256thr, occ 88.6% -> 6232 GB/s, 80.4us  (BEST)
//   R4: MLP-batched, occ 31%        -> 6218 GB/s  (same cap: MLP irrelevant)
//   R7: persistent 1024 blk, occ 69% -> 5203 GB/s (concurrency BELOW knee)
// Law: need ~8K+ concurrent lean warps to saturate ~6.2-6.3 TB/s; flat above.
// This round: persistent at FULL occupancy (1184 blk = 148 SM x 8 CTA,
// 9472 warps, grid-stride over bags) -> removes R3's 2.46 wave transitions
// and the partial tail wave, keeps the proven lean warp shape.

namespace {
constexpr int T = 4;
constexpr long long E = 1000000;
constexpr int D = 128;
constexpr int B = 8192;
constexpr int L = 32;
constexpr int D4 = D / 4;            // 32 float4 per row -> one per lane
constexpr int WARPS_PER_BLOCK = 8;
constexpr int THREADS = WARPS_PER_BLOCK * 32;
constexpr int NUM_BAGS = T * B;      // 32768
constexpr long long IDX_ELEMS = (long long)T * B * L;
constexpr int GRID_BLOCKS = 148 * 8;                    // 1184: full chip at occ 8
constexpr int TOTAL_WARPS = GRID_BLOCKS * WARPS_PER_BLOCK;  // 9472
}

__global__ __launch_bounds__(THREADS)
void embedding_bag_sum_kernel(const int* __restrict__ indices,
                              const float4* __restrict__ weights,
                              float4* __restrict__ out)
{
    const int lane = threadIdx.x & 31;
    const int warp_global = blockIdx.x * WARPS_PER_BLOCK + (threadIdx.x >> 5);

    for (int bag = warp_global; bag < NUM_BAGS; bag += TOTAL_WARPS) {
        const int t = bag >> 13;          // bag / B (B = 8192)
        const int b = bag & (B - 1);

        // Each lane holds one of the 32 bag indices; broadcast via shfl.
        const int my_idx = __ldg(indices + (size_t)bag * L + lane);
        const float4* wt = weights + (size_t)t * (size_t)E * D4;

        float4 acc = make_float4(0.f, 0.f, 0.f, 0.f);

        #pragma unroll
        for (int j = 0; j < L; ++j) {
            const int row = __shfl_sync(0xffffffffu, my_idx, j);
            const float4 v = __ldg(wt + (size_t)row * D4 + lane);
            acc.x += v.x;
            acc.y += v.y;
            acc.z += v.z;
            acc.w += v.w;
        }

        out[((size_t)b * T + t) * D4 + lane] = acc;
    }
}

extern "C" void kernel_launch(void* const* d_in, const int* in_sizes, int n_in,
                              void* d_out, int out_size)
{
    const int*    indices = nullptr;
    const float4* weights = nullptr;
    for (int i = 0; i < n_in; ++i) {
        if ((long long)in_sizes[i] == IDX_ELEMS)
            indices = (const int*)d_in[i];
        else
            weights = (const float4*)d_in[i];
    }
    float4* out = (float4*)d_out;

    embedding_bag_sum_kernel<<<GRID_BLOCKS, THREADS>>>(indices, weights, out);
}

// round 9
// speedup vs baseline: 1.1760x; 1.0785x over previous
#include <cuda_runtime.h>
#include <cstdint>

// T=4 tables, E=1e6 rows, D=128 dim, B=8192 bags, L=32 per bag.
// indices: int32 [T,B,L] (1,048,576 el)   weights: f32 [T,E,D] (512,000,000 el)
// out: f32 [B, T*D]
//
// Evidence:
//   R3: 4096 blk x 8 warps, 1 bag/warp  -> 6232 GB/s, 80.4us (BEST)
//   R4: MLP-batched, occ 31%            -> 6218 GB/s (MLP irrelevant at cap)
//   R7: persistent 1024 blk             -> 5203 GB/s (too few warps)
//   R8: persistent 1184 blk (full chip) -> 5893 GB/s (inter-bag serialization)
// Conclusion: oversubscribed short CTAs win; persistent loses. Traffic is
// ~501MB vs ~473MB floor -> near-optimal. Only slack left: tail/backfill
// granularity -> shrink CTA to 4 warps (8192 blocks x 128 thr), same warp
// shape (warp per bag, lane per float4, shfl-broadcast rows).

namespace {
constexpr int T = 4;
constexpr long long E = 1000000;
constexpr int D = 128;
constexpr int B = 8192;
constexpr int L = 32;
constexpr int D4 = D / 4;            // 32 float4 per row -> one per lane
constexpr int WARPS_PER_BLOCK = 4;   // finer CTA quantum for smoother backfill
constexpr int THREADS = WARPS_PER_BLOCK * 32;
constexpr int NUM_BAGS = T * B;      // 32768
constexpr long long IDX_ELEMS = (long long)T * B * L;
}

__global__ __launch_bounds__(THREADS)
void embedding_bag_sum_kernel(const int* __restrict__ indices,
                              const float4* __restrict__ weights,
                              float4* __restrict__ out)
{
    const int lane = threadIdx.x & 31;
    const int bag = blockIdx.x * WARPS_PER_BLOCK + (threadIdx.x >> 5);

    const int t = bag >> 13;          // bag / B (B = 8192)
    const int b = bag & (B - 1);

    // Each lane holds one of the 32 bag indices; broadcast via shfl.
    const int my_idx = __ldg(indices + (size_t)bag * L + lane);
    const float4* wt = weights + (size_t)t * (size_t)E * D4;

    float4 acc = make_float4(0.f, 0.f, 0.f, 0.f);

    #pragma unroll
    for (int j = 0; j < L; ++j) {
        const int row = __shfl_sync(0xffffffffu, my_idx, j);
        const float4 v = __ldg(wt + (size_t)row * D4 + lane);
        acc.x += v.x;
        acc.y += v.y;
        acc.z += v.z;
        acc.w += v.w;
    }

    // out[b][t*D + d]; lane covers d = lane*4 .. lane*4+3
    out[((size_t)b * T + t) * D4 + lane] = acc;
}

extern "C" void kernel_launch(void* const* d_in, const int* in_sizes, int n_in,
                              void* d_out, int out_size)
{
    const int*    indices = nullptr;
    const float4* weights = nullptr;
    for (int i = 0; i < n_in; ++i) {
        if ((long long)in_sizes[i] == IDX_ELEMS)
            indices = (const int*)d_in[i];
        else
            weights = (const float4*)d_in[i];
    }
    float4* out = (float4*)d_out;

    const int blocks = NUM_BAGS / WARPS_PER_BLOCK;   // 8192
    embedding_bag_sum_kernel<<<blocks, THREADS>>>(indices, weights, out);
}

// round 11
// speedup vs baseline: 1.1806x; 1.0039x over previous
#include <cuda_runtime.h>
#include <cstdint>

// T=4 tables, E=1e6 rows, D=128 dim, B=8192 bags, L=32 per bag.
// indices: int32 [T,B,L] (1,048,576 el)   weights: f32 [T,E,D] (512,000,000 el)
// out: f32 [B, T*D]
//
// FINAL (lock-in of R3 optimum). Session evidence:
//   R3: 4096 blk x 8 warps, 1 bag/warp, 32 regs -> 6232 GB/s, 80.4us  BEST
//   R4: 8-wide MLP batching, 80 regs, occ 31%   -> 6218 GB/s, 80.6us  (flat)
//   R7: persistent 1024 blk                     -> 5203 GB/s, 97us    (worse)
//   R8: persistent 1184 blk (full chip)         -> 5893 GB/s, 89us    (worse)
//   R9: 8192 blk x 4 warps                      -> 6181 GB/s, 82.7us  (worse)
// Ceiling analysis: traffic 501MB vs 473MB unique-row floor (t-major order
// keeps each table's ~118MB unique set L2-resident through its window, so
// duplicates already hit); 6.23 TB/s is the structural random-512B DRAM
// efficiency cap (invariant to occupancy and MLP). This shape IS the roofline.

namespace {
constexpr int T = 4;
constexpr long long E = 1000000;
constexpr int D = 128;
constexpr int B = 8192;
constexpr int L = 32;
constexpr int D4 = D / 4;            // 32 float4 per row -> one per lane
constexpr int WARPS_PER_BLOCK = 8;
constexpr int THREADS = WARPS_PER_BLOCK * 32;
constexpr int NUM_BAGS = T * B;      // 32768
constexpr long long IDX_ELEMS = (long long)T * B * L;   // 1,048,576
}

__global__ __launch_bounds__(THREADS)
void embedding_bag_sum_kernel(const int* __restrict__ indices,
                              const float4* __restrict__ weights,
                              float4* __restrict__ out)
{
    const int warp_in_block = threadIdx.x >> 5;
    const int lane = threadIdx.x & 31;
    const int bag = blockIdx.x * WARPS_PER_BLOCK + warp_in_block;

    const int t = bag >> 13;          // bag / B (B = 8192)
    const int b = bag & (B - 1);

    // Each lane holds one of the 32 bag indices; broadcast via shfl.
    const int my_idx = __ldg(indices + (size_t)bag * L + lane);
    const float4* wt = weights + (size_t)t * (size_t)E * D4;

    float4 acc = make_float4(0.f, 0.f, 0.f, 0.f);

    #pragma unroll
    for (int j = 0; j < L; ++j) {
        const int row = __shfl_sync(0xffffffffu, my_idx, j);
        const float4 v = __ldg(wt + (size_t)row * D4 + lane);
        acc.x += v.x;
        acc.y += v.y;
        acc.z += v.z;
        acc.w += v.w;
    }

    // out[b][t*D + d]; lane covers d = lane*4 .. lane*4+3
    out[((size_t)b * T + t) * D4 + lane] = acc;
}

extern "C" void kernel_launch(void* const* d_in, const int* in_sizes, int n_in,
                              void* d_out, int out_size)
{
    const int*    indices = nullptr;
    const float4* weights = nullptr;
    for (int i = 0; i < n_in; ++i) {
        if ((long long)in_sizes[i] == IDX_ELEMS)
            indices = (const int*)d_in[i];
        else
            weights = (const float4*)d_in[i];
    }
    float4* out = (float4*)d_out;

    const int blocks = NUM_BAGS / WARPS_PER_BLOCK;  // 4096
    embedding_bag_sum_kernel<<<blocks, THREADS>>>(indices, weights, out);
}